// round 7
// baseline (speedup 1.0000x reference)
#include <cuda_runtime.h>
#include <cstdint>

// MeanShift: B=2, C=3, N=9216, 5 iterations.
// w_ij = exp2( (2g*y_i).x_j + (-g*||x_j||^2) + (-g*||y_i||^2) ), g = 50/ln2.
// Per-iter per-SM floors: FMA-pipe ~71.8K cyc == MUFU ~71.8K cyc (balanced).
// R4: kill the pack/unpack MOV tax (alu was 21%) -- load point pairs natively
// as u64 via ld.shared.v2.u64, run ex2 in place on the f32x2 register pair.
// 768 threads = 64 q-slots x 12 j-chunks, 2 queries/thread, grid 144.

#define NPTS 9216
#define NB 2
#define GG 72.13475204444817f   // 50 / ln(2)
#define NSPLIT 12
#define CHUNK (NPTS / NSPLIT)   // 768 points per chunk

typedef unsigned long long u64;

__device__ float4 g_pts[NB * NPTS];      // [2*jp+0]={x0,x1,y0,y1}, [2*jp+1]={z0,z1,b0,b1}
__device__ float4 g_y[2][NB * NPTS];

__device__ __forceinline__ u64 pk2(float a, float b) {
    u64 r; asm("mov.b64 %0, {%1,%2};" : "=l"(r) : "f"(a), "f"(b)); return r;
}
__device__ __forceinline__ void upk2(u64 v, float& a, float& b) {
    asm("mov.b64 {%0,%1}, %2;" : "=f"(a), "=f"(b) : "l"(v));
}
__device__ __forceinline__ u64 fma2(u64 a, u64 b, u64 c) {
    u64 d; asm("fma.rn.f32x2 %0, %1, %2, %3;" : "=l"(d) : "l"(a), "l"(b), "l"(c)); return d;
}
__device__ __forceinline__ u64 add2(u64 a, u64 b) {
    u64 d; asm("add.rn.f32x2 %0, %1, %2;" : "=l"(d) : "l"(a), "l"(b)); return d;
}
// exp2 on both halves of an f32x2 pair, in place (self-moves fold away).
__device__ __forceinline__ void ex2_pair(u64& t) {
    asm("{\n\t"
        ".reg .f32 lo, hi;\n\t"
        "mov.b64 {lo, hi}, %0;\n\t"
        "ex2.approx.ftz.f32 lo, lo;\n\t"
        "ex2.approx.ftz.f32 hi, hi;\n\t"
        "mov.b64 %0, {lo, hi};\n\t"
        "}" : "+l"(t));
}
__device__ __forceinline__ void lds_2u64(unsigned addr, u64& a, u64& b) {
    asm("ld.shared.v2.u64 {%0, %1}, [%2];" : "=l"(a), "=l"(b) : "r"(addr));
}

__global__ void prep_kernel(const float* __restrict__ x) {
    int idx = blockIdx.x * blockDim.x + threadIdx.x;
    if (idx >= NB * NPTS) return;
    int b = idx / NPTS, n = idx - b * NPTS;
    float px = x[(b * 3 + 0) * NPTS + n];
    float py = x[(b * 3 + 1) * NPTS + n];
    float pz = x[(b * 3 + 2) * NPTS + n];
    float bn = -GG * (px * px + py * py + pz * pz);
    int jp = n >> 1, l = n & 1;
    float* base = (float*)&g_pts[b * NPTS + 2 * jp];
    base[0 + l] = px;   // {x0,x1, y0,y1}
    base[2 + l] = py;
    base[4 + l] = pz;   // {z0,z1, b0,b1}
    base[6 + l] = bn;
    g_y[0][b * NPTS + n] = make_float4(px, py, pz, 0.f);
}

// Grid: (72 query-tiles, 2 batches), 768 threads = 64 q-slots x 12 j-chunks,
// each thread owns 2 queries (ql, ql+64). Chunk id uniform per warp -> all
// LDS.128 are full-warp broadcasts.
__global__ __launch_bounds__(768, 1) void iter_kernel(int src, int dst, float* __restrict__ out) {
    extern __shared__ float4 sm[];          // [0,NPTS): points, then NSPLIT*128 partials
    float4* psum = sm + NPTS;
    const int b = blockIdx.y;

    const float4* gp = g_pts + b * NPTS;
    for (int i = threadIdx.x; i < NPTS; i += 768) sm[i] = gp[i];
    __syncthreads();

    const int ql = threadIdx.x & 63;        // query slot (q0=ql, q1=ql+64)
    const int s = threadIdx.x >> 6;         // j-chunk id (uniform within warp)
    const int qg0 = blockIdx.x * 128 + ql;
    const int qg1 = qg0 + 64;

    const float tg = 2.0f * GG;
    float4 y0 = g_y[src][b * NPTS + qg0];
    float4 y1 = g_y[src][b * NPTS + qg1];
    const u64 ax0 = pk2(tg * y0.x, tg * y0.x);
    const u64 ay0 = pk2(tg * y0.y, tg * y0.y);
    const u64 az0 = pk2(tg * y0.z, tg * y0.z);
    const float p0 = -GG * (y0.x * y0.x + y0.y * y0.y + y0.z * y0.z);
    const u64 pp0 = pk2(p0, p0);
    const u64 ax1 = pk2(tg * y1.x, tg * y1.x);
    const u64 ay1 = pk2(tg * y1.y, tg * y1.y);
    const u64 az1 = pk2(tg * y1.z, tg * y1.z);
    const float p1 = -GG * (y1.x * y1.x + y1.y * y1.y + y1.z * y1.z);
    const u64 pp1 = pk2(p1, p1);

    u64 a0x = 0ull, a0y = 0ull, a0z = 0ull, a0w = 0ull;
    u64 a1x = 0ull, a1y = 0ull, a1z = 0ull, a1w = 0ull;

    // Shared-window byte address of this warp's chunk (CHUNK float4s).
    unsigned saddr = (unsigned)__cvta_generic_to_shared(sm + s * CHUNK);

    #pragma unroll 2
    for (int i = 0; i < CHUNK / 2; i++) {   // 384 steps, 2 points x 2 queries
        u64 xx, yy, zz, bb;
        lds_2u64(saddr + 32u * i, xx, yy);        // {x0,x1},{y0,y1}
        lds_2u64(saddr + 32u * i + 16u, zz, bb);  // {z0,z1},{b0,b1}

        u64 t0 = add2(bb, pp0);
        t0 = fma2(az0, zz, t0);
        t0 = fma2(ay0, yy, t0);
        t0 = fma2(ax0, xx, t0);
        u64 t1 = add2(bb, pp1);
        t1 = fma2(az1, zz, t1);
        t1 = fma2(ay1, yy, t1);
        t1 = fma2(ax1, xx, t1);

        ex2_pair(t0);                       // 4x MUFU EX2 total, in place
        ex2_pair(t1);

        a0x = fma2(t0, xx, a0x);
        a0y = fma2(t0, yy, a0y);
        a0z = fma2(t0, zz, a0z);
        a0w = add2(a0w, t0);
        a1x = fma2(t1, xx, a1x);
        a1y = fma2(t1, yy, a1y);
        a1z = fma2(t1, zz, a1z);
        a1w = add2(a1w, t1);
    }

    float e0, e1;
    upk2(a0x, e0, e1); float s0x = e0 + e1;
    upk2(a0y, e0, e1); float s0y = e0 + e1;
    upk2(a0z, e0, e1); float s0z = e0 + e1;
    upk2(a0w, e0, e1); float s0w = e0 + e1;
    psum[s * 128 + ql] = make_float4(s0x, s0y, s0z, s0w);
    upk2(a1x, e0, e1); float s1x = e0 + e1;
    upk2(a1y, e0, e1); float s1y = e0 + e1;
    upk2(a1z, e0, e1); float s1z = e0 + e1;
    upk2(a1w, e0, e1); float s1w = e0 + e1;
    psum[s * 128 + ql + 64] = make_float4(s1x, s1y, s1z, s1w);
    __syncthreads();

    // Reduce the NSPLIT chunk-partials per query.
    if (threadIdx.x < 128) {
        float4 a = psum[threadIdx.x];
        #pragma unroll
        for (int k = 1; k < NSPLIT; k++) {
            float4 p2 = psum[k * 128 + threadIdx.x];
            a.x += p2.x; a.y += p2.y; a.z += p2.z; a.w += p2.w;
        }
        float inv = __fdividef(1.0f, a.w);
        float nx = a.x * inv, ny = a.y * inv, nz = a.z * inv;
        int qi = blockIdx.x * 128 + threadIdx.x;
        g_y[dst][b * NPTS + qi] = make_float4(nx, ny, nz, 0.f);
        if (out) {
            out[(b * 3 + 0) * NPTS + qi] = nx;
            out[(b * 3 + 1) * NPTS + qi] = ny;
            out[(b * 3 + 2) * NPTS + qi] = nz;
        }
    }
}

extern "C" void kernel_launch(void* const* d_in, const int* in_sizes, int n_in,
                              void* d_out, int out_size) {
    const float* x = (const float*)d_in[0];
    float* out = (float*)d_out;

    const size_t smem = (size_t)(NPTS + NSPLIT * 128) * sizeof(float4);  // 172032 B
    cudaFuncSetAttribute(iter_kernel, cudaFuncAttributeMaxDynamicSharedMemorySize, (int)smem);

    prep_kernel<<<(NB * NPTS + 255) / 256, 256>>>(x);

    dim3 grid(72, NB);
    for (int it = 0; it < 5; it++) {
        iter_kernel<<<grid, 768, smem>>>(it & 1, (it & 1) ^ 1, (it == 4) ? out : nullptr);
    }
}

// round 9
// speedup vs baseline: 1.0843x; 1.0843x over previous
#include <cuda_runtime.h>
#include <cuda_fp16.h>
#include <cstdint>

// MeanShift: B=2, C=3, N=9216, 5 iters.
// w_ij = exp2( (2g*y_i).x_j - g||x_j||^2 - g||y_i||^2 ), g = 50/ln2.
// Accumulation offloaded to HMMA (mma.sync m16n8k16 f16*f16+f32, sm_80+ -- no
// tcgen05 needed): D[16q x 8] += W[16x16] x B[16pts x 8feat], features =
// (x,y,z,1,0,0,0,0). Weights are computed straight into the A-fragment layout
// (rows g,g+8 / k-cols 2t,2t+1,+8) from f32 args + ex2.approx.f16x2.
// 24 warps: 8 query-groups (16 q each) x 3 j-splits, barrier-free mainloop.

#define NPTS 9216
#define NB 2
#define GG 72.13475204444817f
#define TPB 768
#define NJS 3
#define WINS_PER_JS 192          // 576 windows of 16 points, split 3 ways

typedef unsigned long long u64;
typedef unsigned int u32;

__device__ float4 g_pts[NB * NPTS];   // [2*jp]={x0,x1,y0,y1}, [2*jp+1]={z0,z1,b0,b1}
__device__ float4 g_y[2][NB * NPTS];

#define SO_PSUM 147456           // float4 psum[NJS][128]
#define SMEMSZ  (147456 + NJS * 128 * 16)

static __device__ __forceinline__ u64 pk2(float a, float b) {
    u64 r; asm("mov.b64 %0,{%1,%2};" : "=l"(r) : "f"(a), "f"(b)); return r;
}
static __device__ __forceinline__ u64 fma2(u64 a, u64 b, u64 c) {
    u64 d; asm("fma.rn.f32x2 %0,%1,%2,%3;" : "=l"(d) : "l"(a), "l"(b), "l"(c)); return d;
}
static __device__ __forceinline__ u64 add2(u64 a, u64 b) {
    u64 d; asm("add.rn.f32x2 %0,%1,%2;" : "=l"(d) : "l"(a), "l"(b)); return d;
}
static __device__ __forceinline__ void lds2(u32 a, u64& x, u64& y) {
    asm volatile("ld.shared.v2.u64 {%0,%1},[%2];" : "=l"(x), "=l"(y) : "r"(a));
}
static __device__ __forceinline__ u64 lds1(u32 a) {
    u64 v; asm volatile("ld.shared.b64 %0,[%1];" : "=l"(v) : "r"(a)); return v;
}
// f32x2 arg -> fp16x2 weight pair (lo stays lo): cvt + one ex2.approx.f16x2.
static __device__ __forceinline__ u32 wgt2(u64 t) {
    u32 h;
    asm("{\n\t.reg .f32 lo,hi;\n\tmov.b64 {lo,hi},%1;\n\t"
        "cvt.rn.f16x2.f32 %0,hi,lo;\n\tex2.approx.f16x2 %0,%0;\n\t}" : "=r"(h) : "l"(t));
    return h;
}
static __device__ __forceinline__ u32 cvth2(u64 t) {
    u32 h;
    asm("{\n\t.reg .f32 lo,hi;\n\tmov.b64 {lo,hi},%1;\n\tcvt.rn.f16x2.f32 %0,hi,lo;\n\t}"
        : "=r"(h) : "l"(t));
    return h;
}
static __device__ __forceinline__ void mma16816(
    float& c0, float& c1, float& c2, float& c3,
    u32 a0, u32 a1, u32 a2, u32 a3, u32 b0, u32 b1) {
    asm volatile("mma.sync.aligned.m16n8k16.row.col.f32.f16.f16.f32 "
        "{%0,%1,%2,%3}, {%4,%5,%6,%7}, {%8,%9}, {%0,%1,%2,%3};"
        : "+f"(c0), "+f"(c1), "+f"(c2), "+f"(c3)
        : "r"(a0), "r"(a1), "r"(a2), "r"(a3), "r"(b0), "r"(b1));
}

__global__ void prep_kernel(const float* __restrict__ x) {
    int idx = blockIdx.x * blockDim.x + threadIdx.x;
    if (idx >= NB * NPTS) return;
    int b = idx / NPTS, n = idx - b * NPTS;
    float px = x[(b * 3 + 0) * NPTS + n];
    float py = x[(b * 3 + 1) * NPTS + n];
    float pz = x[(b * 3 + 2) * NPTS + n];
    float bn = -GG * (px * px + py * py + pz * pz);
    int jp = n >> 1, l = n & 1;
    float* base = (float*)&g_pts[b * NPTS + 2 * jp];
    base[0 + l] = px; base[2 + l] = py; base[4 + l] = pz; base[6 + l] = bn;
    g_y[0][b * NPTS + n] = make_float4(px, py, pz, 0.f);
}

__global__ __launch_bounds__(TPB, 1) void iter_kernel(int src, int dst, float* __restrict__ out) {
    extern __shared__ __align__(16) unsigned char smem[];
    const int tid = threadIdx.x, wid = tid >> 5, lane = tid & 31;
    const int g = lane >> 2, t = lane & 3;
    const int b = blockIdx.y, tile = blockIdx.x;
    u32 sb = (u32)__cvta_generic_to_shared(smem);

    {   // stage points (147456 B)
        const float4* gp = g_pts + b * NPTS;
        float4* sp = (float4*)smem;
        for (int i = tid; i < NPTS; i += TPB) sp[i] = gp[i];
    }
    __syncthreads();

    const int qg = wid & 7;            // query group: 16 queries
    const int js = wid >> 3;           // j-split 0..2
    const int q0l = qg * 16 + g;       // local query of row g
    const int q1l = q0l + 8;           // local query of row g+8

    const float tg = 2.0f * GG;
    float4 y0 = g_y[src][b * NPTS + tile * 128 + q0l];
    float4 y1 = g_y[src][b * NPTS + tile * 128 + q1l];
    const u64 ax0 = pk2(tg * y0.x, tg * y0.x);
    const u64 ay0 = pk2(tg * y0.y, tg * y0.y);
    const u64 az0 = pk2(tg * y0.z, tg * y0.z);
    const float p0 = -GG * (y0.x * y0.x + y0.y * y0.y + y0.z * y0.z);
    const u64 pp0 = pk2(p0, p0);
    const u64 ax1 = pk2(tg * y1.x, tg * y1.x);
    const u64 ay1 = pk2(tg * y1.y, tg * y1.y);
    const u64 az1 = pk2(tg * y1.z, tg * y1.z);
    const float p1 = -GG * (y1.x * y1.x + y1.y * y1.y + y1.z * y1.z);
    const u64 pp1 = pk2(p1, p1);

    // B-fragment select masks: col g -> feature x/y/z (load), 1.0 (g==3), 0.
    const u32 mand = (g < 3) ? 0xFFFFFFFFu : 0u;
    const u32 mor  = (g == 3) ? 0x3C003C00u : 0u;
    const u32 gm8  = (u32)((g < 3 ? g : 2) * 8);

    float c0 = 0.f, c1 = 0.f, c2 = 0.f, c3 = 0.f;

    // 192 windows x 16 points, no block barriers in the loop.
    u32 base = sb + (u32)(js * WINS_PER_JS) * 256u;
    for (int w = 0; w < WINS_PER_JS; w++, base += 256u) {
        u32 pa = base + 32u * (u32)t;
        u64 xx0, yy0, zz0, bb0, xx1, yy1, zz1, bb1;
        lds2(pa, xx0, yy0);
        lds2(pa + 16u, zz0, bb0);
        lds2(pa + 128u, xx1, yy1);
        lds2(pa + 144u, zz1, bb1);

        // args: (row, pair) = (g,p0) (g+8,p0) (g,p1) (g+8,p1)
        u64 t00 = fma2(ax0, xx0, fma2(ay0, yy0, fma2(az0, zz0, add2(bb0, pp0))));
        u64 t10 = fma2(ax1, xx0, fma2(ay1, yy0, fma2(az1, zz0, add2(bb0, pp1))));
        u64 t01 = fma2(ax0, xx1, fma2(ay0, yy1, fma2(az0, zz1, add2(bb1, pp0))));
        u64 t11 = fma2(ax1, xx1, fma2(ay1, yy1, fma2(az1, zz1, add2(bb1, pp1))));

        u32 a0 = wgt2(t00);   // row g,   k=2t,2t+1
        u32 a1 = wgt2(t10);   // row g+8, k=2t,2t+1
        u32 a2 = wgt2(t01);   // row g,   k=2t+8,2t+9
        u32 a3 = wgt2(t11);   // row g+8, k=2t+8,2t+9

        // B frag: feature g of points {2t,2t+1} and {2t+8,2t+9}
        u32 b0 = (cvth2(lds1(pa + gm8)) & mand) | mor;
        u32 b1 = (cvth2(lds1(pa + 128u + gm8)) & mand) | mor;

        mma16816(c0, c1, c2, c3, a0, a1, a2, a3, b0, b1);
    }

    // D: c0,c1 = row g cols {2t,2t+1}; c2,c3 = row g+8. Cols: 0=x,1=y,2=z,3=den.
    float* ps = (float*)(smem + SO_PSUM);
    if (t == 0) {
        ps[(js * 128 + q0l) * 4 + 0] = c0; ps[(js * 128 + q0l) * 4 + 1] = c1;
        ps[(js * 128 + q1l) * 4 + 0] = c2; ps[(js * 128 + q1l) * 4 + 1] = c3;
    } else if (t == 1) {
        ps[(js * 128 + q0l) * 4 + 2] = c0; ps[(js * 128 + q0l) * 4 + 3] = c1;
        ps[(js * 128 + q1l) * 4 + 2] = c2; ps[(js * 128 + q1l) * 4 + 3] = c3;
    }
    __syncthreads();

    if (tid < 128) {
        float4* pv = (float4*)(smem + SO_PSUM);
        float4 a = pv[tid];
        float4 s1 = pv[128 + tid];
        float4 s2 = pv[256 + tid];
        a.x += s1.x + s2.x; a.y += s1.y + s2.y;
        a.z += s1.z + s2.z; a.w += s1.w + s2.w;
        float inv = __fdividef(1.0f, a.w);
        float nx = a.x * inv, ny = a.y * inv, nz = a.z * inv;
        int qi = tile * 128 + tid;
        g_y[dst][b * NPTS + qi] = make_float4(nx, ny, nz, 0.f);
        if (out) {
            out[(b * 3 + 0) * NPTS + qi] = nx;
            out[(b * 3 + 1) * NPTS + qi] = ny;
            out[(b * 3 + 2) * NPTS + qi] = nz;
        }
    }
}

extern "C" void kernel_launch(void* const* d_in, const int* in_sizes, int n_in,
                              void* d_out, int out_size) {
    const float* x = (const float*)d_in[0];
    float* out = (float*)d_out;

    cudaFuncSetAttribute(iter_kernel, cudaFuncAttributeMaxDynamicSharedMemorySize, SMEMSZ);

    prep_kernel<<<(NB * NPTS + 255) / 256, 256>>>(x);

    dim3 grid(72, NB);
    for (int it = 0; it < 5; it++) {
        iter_kernel<<<grid, TPB, SMEMSZ>>>(it & 1, (it & 1) ^ 1, (it == 4) ? out : nullptr);
    }
}

// round 10
// speedup vs baseline: 1.3136x; 1.2115x over previous
#include <cuda_runtime.h>
#include <cuda_fp16.h>
#include <cstdint>

// MeanShift: B=2, C=3, N=9216, 5 iters.
// w_ij = exp2( (2g*y_i).x_j - g||x_j||^2 - g||y_i||^2 ), g = 50/ln2.
// HMMA accumulation (mma.sync m16n8k16 f16xf16+f32): D[16q x 8] += W[16x16] x
// B[16pts x 8feat], features (x,y,z,1,0,0,0,0). R10: each warp owns TWO query
// groups (32 q) per 16-pt window -> 4 LDS.128 amortized over 2 MMAs, and the
// B fragment comes from registers (select of xx/yy/zz) instead of extra LDS.
// 16 warps = 4 query-pairs x 4 j-splits, barrier-free mainloop.

#define NPTS 9216
#define NB 2
#define GG 72.13475204444817f
#define TPB 512
#define NJS 4
#define WINS_PER_JS 144          // 576 windows of 16 points, split 4 ways

typedef unsigned long long u64;
typedef unsigned int u32;

__device__ float4 g_pts[NB * NPTS];   // [2*jp]={x0,x1,y0,y1}, [2*jp+1]={z0,z1,b0,b1}
__device__ float4 g_y[2][NB * NPTS];

#define SO_PSUM 147456           // float4 psum[NJS][128]
#define SMEMSZ  (147456 + NJS * 128 * 16)

static __device__ __forceinline__ u64 pk2(float a, float b) {
    u64 r; asm("mov.b64 %0,{%1,%2};" : "=l"(r) : "f"(a), "f"(b)); return r;
}
static __device__ __forceinline__ u64 fma2(u64 a, u64 b, u64 c) {
    u64 d; asm("fma.rn.f32x2 %0,%1,%2,%3;" : "=l"(d) : "l"(a), "l"(b), "l"(c)); return d;
}
static __device__ __forceinline__ u64 add2(u64 a, u64 b) {
    u64 d; asm("add.rn.f32x2 %0,%1,%2;" : "=l"(d) : "l"(a), "l"(b)); return d;
}
static __device__ __forceinline__ void lds2(u32 a, u64& x, u64& y) {
    asm volatile("ld.shared.v2.u64 {%0,%1},[%2];" : "=l"(x), "=l"(y) : "r"(a));
}
// f32x2 arg -> fp16x2 weight pair (lo stays lo): cvt + one ex2.approx.f16x2.
static __device__ __forceinline__ u32 wgt2(u64 t) {
    u32 h;
    asm("{\n\t.reg .f32 lo,hi;\n\tmov.b64 {lo,hi},%1;\n\t"
        "cvt.rn.f16x2.f32 %0,hi,lo;\n\tex2.approx.f16x2 %0,%0;\n\t}" : "=r"(h) : "l"(t));
    return h;
}
static __device__ __forceinline__ u32 cvth2(u64 t) {
    u32 h;
    asm("{\n\t.reg .f32 lo,hi;\n\tmov.b64 {lo,hi},%1;\n\tcvt.rn.f16x2.f32 %0,hi,lo;\n\t}"
        : "=r"(h) : "l"(t));
    return h;
}
static __device__ __forceinline__ void mma16816(
    float& c0, float& c1, float& c2, float& c3,
    u32 a0, u32 a1, u32 a2, u32 a3, u32 b0, u32 b1) {
    asm volatile("mma.sync.aligned.m16n8k16.row.col.f32.f16.f16.f32 "
        "{%0,%1,%2,%3}, {%4,%5,%6,%7}, {%8,%9}, {%0,%1,%2,%3};"
        : "+f"(c0), "+f"(c1), "+f"(c2), "+f"(c3)
        : "r"(a0), "r"(a1), "r"(a2), "r"(a3), "r"(b0), "r"(b1));
}

__global__ void prep_kernel(const float* __restrict__ x) {
    int idx = blockIdx.x * blockDim.x + threadIdx.x;
    if (idx >= NB * NPTS) return;
    int b = idx / NPTS, n = idx - b * NPTS;
    float px = x[(b * 3 + 0) * NPTS + n];
    float py = x[(b * 3 + 1) * NPTS + n];
    float pz = x[(b * 3 + 2) * NPTS + n];
    float bn = -GG * (px * px + py * py + pz * pz);
    int jp = n >> 1, l = n & 1;
    float* base = (float*)&g_pts[b * NPTS + 2 * jp];
    base[0 + l] = px; base[2 + l] = py; base[4 + l] = pz; base[6 + l] = bn;
    g_y[0][b * NPTS + n] = make_float4(px, py, pz, 0.f);
}

__global__ __launch_bounds__(TPB, 1) void iter_kernel(int src, int dst, float* __restrict__ out) {
    extern __shared__ __align__(16) unsigned char smem[];
    const int tid = threadIdx.x, wid = tid >> 5, lane = tid & 31;
    const int g = lane >> 2, t = lane & 3;
    const int b = blockIdx.y, tile = blockIdx.x;
    u32 sb = (u32)__cvta_generic_to_shared(smem);

    {   // stage points (147456 B)
        const float4* gp = g_pts + b * NPTS;
        float4* sp = (float4*)smem;
        for (int i = tid; i < NPTS; i += TPB) sp[i] = gp[i];
    }
    __syncthreads();

    const int qp = wid & 3;            // query-pair: 32 queries
    const int js = wid >> 2;           // j-split 0..3
    const int qA0 = qp * 32 + g;       // MMA-A rows g, g+8
    const int qA1 = qA0 + 8;
    const int qB0 = qA0 + 16;          // MMA-B rows
    const int qB1 = qA0 + 24;

    const float tg = 2.0f * GG;
    u64 axA0, ayA0, azA0, ppA0, axA1, ayA1, azA1, ppA1;
    u64 axB0, ayB0, azB0, ppB0, axB1, ayB1, azB1, ppB1;
    {
        float4 y;
        y = g_y[src][b * NPTS + tile * 128 + qA0];
        axA0 = pk2(tg * y.x, tg * y.x); ayA0 = pk2(tg * y.y, tg * y.y);
        azA0 = pk2(tg * y.z, tg * y.z);
        float p = -GG * (y.x * y.x + y.y * y.y + y.z * y.z); ppA0 = pk2(p, p);
        y = g_y[src][b * NPTS + tile * 128 + qA1];
        axA1 = pk2(tg * y.x, tg * y.x); ayA1 = pk2(tg * y.y, tg * y.y);
        azA1 = pk2(tg * y.z, tg * y.z);
        p = -GG * (y.x * y.x + y.y * y.y + y.z * y.z); ppA1 = pk2(p, p);
        y = g_y[src][b * NPTS + tile * 128 + qB0];
        axB0 = pk2(tg * y.x, tg * y.x); ayB0 = pk2(tg * y.y, tg * y.y);
        azB0 = pk2(tg * y.z, tg * y.z);
        p = -GG * (y.x * y.x + y.y * y.y + y.z * y.z); ppB0 = pk2(p, p);
        y = g_y[src][b * NPTS + tile * 128 + qB1];
        axB1 = pk2(tg * y.x, tg * y.x); ayB1 = pk2(tg * y.y, tg * y.y);
        azB1 = pk2(tg * y.z, tg * y.z);
        p = -GG * (y.x * y.x + y.y * y.y + y.z * y.z); ppB1 = pk2(p, p);
    }

    // B-fragment build: feature g of the point pair, from registers.
    const u32 mand = (g < 3) ? 0xFFFFFFFFu : 0u;
    const u32 mor  = (g == 3) ? 0x3C003C00u : 0u;

    float cA0 = 0.f, cA1 = 0.f, cA2 = 0.f, cA3 = 0.f;
    float cB0 = 0.f, cB1 = 0.f, cB2 = 0.f, cB3 = 0.f;

    // 144 windows x 16 points, no block barriers in the loop.
    u32 base = sb + (u32)(js * WINS_PER_JS) * 256u + 32u * (u32)t;
    for (int w = 0; w < WINS_PER_JS; w++, base += 256u) {
        u64 xx0, yy0, zz0, bb0, xx1, yy1, zz1, bb1;
        lds2(base, xx0, yy0);
        lds2(base + 16u, zz0, bb0);
        lds2(base + 128u, xx1, yy1);
        lds2(base + 144u, zz1, bb1);

        // 8 args: 4 query rows x 2 point pairs.
        u64 tA00 = fma2(axA0, xx0, fma2(ayA0, yy0, fma2(azA0, zz0, add2(bb0, ppA0))));
        u64 tA10 = fma2(axA1, xx0, fma2(ayA1, yy0, fma2(azA1, zz0, add2(bb0, ppA1))));
        u64 tB00 = fma2(axB0, xx0, fma2(ayB0, yy0, fma2(azB0, zz0, add2(bb0, ppB0))));
        u64 tB10 = fma2(axB1, xx0, fma2(ayB1, yy0, fma2(azB1, zz0, add2(bb0, ppB1))));
        u64 tA01 = fma2(axA0, xx1, fma2(ayA0, yy1, fma2(azA0, zz1, add2(bb1, ppA0))));
        u64 tA11 = fma2(axA1, xx1, fma2(ayA1, yy1, fma2(azA1, zz1, add2(bb1, ppA1))));
        u64 tB01 = fma2(axB0, xx1, fma2(ayB0, yy1, fma2(azB0, zz1, add2(bb1, ppB0))));
        u64 tB11 = fma2(axB1, xx1, fma2(ayB1, yy1, fma2(azB1, zz1, add2(bb1, ppB1))));

        // Shared B fragment (same points, same features for both MMAs).
        u64 sel0 = (g == 0) ? xx0 : (g == 1) ? yy0 : zz0;
        u64 sel1 = (g == 0) ? xx1 : (g == 1) ? yy1 : zz1;
        u32 b0 = (cvth2(sel0) & mand) | mor;
        u32 b1 = (cvth2(sel1) & mand) | mor;

        mma16816(cA0, cA1, cA2, cA3,
                 wgt2(tA00), wgt2(tA10), wgt2(tA01), wgt2(tA11), b0, b1);
        mma16816(cB0, cB1, cB2, cB3,
                 wgt2(tB00), wgt2(tB10), wgt2(tB01), wgt2(tB11), b0, b1);
    }

    // D rows: cX0,cX1 = row q?0 cols {2t,2t+1}; cX2,cX3 = row q?1.
    float* ps = (float*)(smem + SO_PSUM);
    if (t == 0) {
        ps[(js * 128 + qA0) * 4 + 0] = cA0; ps[(js * 128 + qA0) * 4 + 1] = cA1;
        ps[(js * 128 + qA1) * 4 + 0] = cA2; ps[(js * 128 + qA1) * 4 + 1] = cA3;
        ps[(js * 128 + qB0) * 4 + 0] = cB0; ps[(js * 128 + qB0) * 4 + 1] = cB1;
        ps[(js * 128 + qB1) * 4 + 0] = cB2; ps[(js * 128 + qB1) * 4 + 1] = cB3;
    } else if (t == 1) {
        ps[(js * 128 + qA0) * 4 + 2] = cA0; ps[(js * 128 + qA0) * 4 + 3] = cA1;
        ps[(js * 128 + qA1) * 4 + 2] = cA2; ps[(js * 128 + qA1) * 4 + 3] = cA3;
        ps[(js * 128 + qB0) * 4 + 2] = cB0; ps[(js * 128 + qB0) * 4 + 3] = cB1;
        ps[(js * 128 + qB1) * 4 + 2] = cB2; ps[(js * 128 + qB1) * 4 + 3] = cB3;
    }
    __syncthreads();

    if (tid < 128) {
        float4* pv = (float4*)(smem + SO_PSUM);
        float4 a = pv[tid];
        #pragma unroll
        for (int k = 1; k < NJS; k++) {
            float4 s = pv[k * 128 + tid];
            a.x += s.x; a.y += s.y; a.z += s.z; a.w += s.w;
        }
        float inv = __fdividef(1.0f, a.w);
        float nx = a.x * inv, ny = a.y * inv, nz = a.z * inv;
        int qi = tile * 128 + tid;
        g_y[dst][b * NPTS + qi] = make_float4(nx, ny, nz, 0.f);
        if (out) {
            out[(b * 3 + 0) * NPTS + qi] = nx;
            out[(b * 3 + 1) * NPTS + qi] = ny;
            out[(b * 3 + 2) * NPTS + qi] = nz;
        }
    }
}

extern "C" void kernel_launch(void* const* d_in, const int* in_sizes, int n_in,
                              void* d_out, int out_size) {
    const float* x = (const float*)d_in[0];
    float* out = (float*)d_out;

    cudaFuncSetAttribute(iter_kernel, cudaFuncAttributeMaxDynamicSharedMemorySize, SMEMSZ);

    prep_kernel<<<(NB * NPTS + 255) / 256, 256>>>(x);

    dim3 grid(72, NB);
    for (int it = 0; it < 5; it++) {
        iter_kernel<<<grid, TPB, SMEMSZ>>>(it & 1, (it & 1) ^ 1, (it == 4) ? out : nullptr);
    }
}